// round 6
// baseline (speedup 1.0000x reference)
#include <cuda_runtime.h>
#include <cuda_bf16.h>
#include <cstdint>

#define BB 8
#define CC 256
#define NN 2048

// ---------------- scratch (device globals; no allocs) ----------------------
__device__ __nv_bfloat16 g_Xh[BB * NN * CC], g_Xl[BB * NN * CC];   // xT [b][n][c]
__device__ __nv_bfloat16 g_Wh[3 * CC * CC],  g_Wl[3 * CC * CC];    // Wq,Wk,Wv split
__device__ __nv_bfloat16 g_Qh[BB * NN * CC], g_Ql[BB * NN * CC];   // [b][n][c]
__device__ __nv_bfloat16 g_Kh[BB * NN * CC], g_Kl[BB * NN * CC];   // [b][m][c]
__device__ __nv_bfloat16 g_Vh[BB * CC * NN], g_Vl[BB * CC * NN];   // [b][c][m]

// ---------------- PTX helpers (baseline PTX only) ---------------------------
__device__ __forceinline__ uint32_t smem_u32(const void* p) {
    uint32_t a;
    asm("{ .reg .u64 t; cvta.to.shared.u64 t, %1; cvt.u32.u64 %0, t; }"
        : "=r"(a) : "l"(p));
    return a;
}

#define CP_ASYNC16(dst, src) \
    asm volatile("cp.async.cg.shared.global [%0], [%1], 16;" \
                 :: "r"(dst), "l"(src) : "memory")
#define CP_COMMIT() asm volatile("cp.async.commit_group;" ::: "memory")
#define CP_WAIT(n)  asm volatile("cp.async.wait_group %0;" :: "n"(n) : "memory")

#define LDSM_X4(r0, r1, r2, r3, addr) \
    asm volatile("ldmatrix.sync.aligned.m8n8.x4.shared.b16 {%0,%1,%2,%3}, [%4];" \
                 : "=r"(r0), "=r"(r1), "=r"(r2), "=r"(r3) : "r"(addr))

#define MMA16816(c, a, b0, b1) \
    asm volatile("mma.sync.aligned.m16n8k16.row.col.f32.bf16.bf16.f32 " \
                 "{%0,%1,%2,%3}, {%4,%5,%6,%7}, {%8,%9}, {%0,%1,%2,%3};" \
                 : "+f"((c)[0]), "+f"((c)[1]), "+f"((c)[2]), "+f"((c)[3]) \
                 : "r"((a)[0]), "r"((a)[1]), "r"((a)[2]), "r"((a)[3]), \
                   "r"(b0), "r"(b1))

__device__ __forceinline__ __nv_bfloat16 bsplit_hi(float v) { return __float2bfloat16(v); }
__device__ __forceinline__ __nv_bfloat16 bsplit_lo(float v, __nv_bfloat16 h) {
    return __float2bfloat16(v - __bfloat162float(h));
}

#define ROW_STRIDE 80
#define TILE_BYTES 10240            // 128 rows * 80 B
// qkv kernel smem
#define QB_TILE    5120             // 64 * 80
#define QBUF       (2 * TILE_BYTES + 6 * QB_TILE)   // 51200
#define QSMEM      (2 * QBUF)                       // 102400

// flash kernel smem map (byte offsets in dynamic smem)
#define F_QH    0u              // 8 chunks x 5120
#define F_QL    40960u
#define F_PH    81920u          // 4 chunks x 5120
#define F_PL    102400u
#define F_STR   122880u         // 81920-byte stream area (K x2 / V x2 / staging)
#define F_RED   204800u         // 1024 B reductions
#define F_SMEM  205824u

// ---------------------------------------------------------------------------
// xsplit: x [b][c][n] fp32 -> xT hi/lo [b][n][c] bf16
// ---------------------------------------------------------------------------
__global__ __launch_bounds__(256) void xsplit_kernel(const float* __restrict__ x)
{
    __shared__ float t[32][33];
    const int n0 = blockIdx.x * 32;
    const int c0 = blockIdx.y * 32;
    const int b  = blockIdx.z;
    const int tx = threadIdx.x & 31;
    const int ty = threadIdx.x >> 5;

    #pragma unroll
    for (int k = 0; k < 4; k++)
        t[ty + k * 8][tx] = x[((size_t)b * CC + c0 + ty + k * 8) * NN + n0 + tx];
    __syncthreads();
    #pragma unroll
    for (int k = 0; k < 4; k++) {
        const float v = t[tx][ty + k * 8];
        const __nv_bfloat16 h = bsplit_hi(v);
        const size_t idx = ((size_t)b * NN + n0 + ty + k * 8) * CC + c0 + tx;
        g_Xh[idx] = h;
        g_Xl[idx] = bsplit_lo(v, h);
    }
}

// ---------------------------------------------------------------------------
// wsplit
// ---------------------------------------------------------------------------
__global__ __launch_bounds__(256) void wsplit_kernel(
    const float* __restrict__ Wq, const float* __restrict__ Wk,
    const float* __restrict__ Wv)
{
    const int m = blockIdx.y;
    const int e = blockIdx.x * 256 + threadIdx.x;
    const float v = (m == 0 ? Wq : (m == 1 ? Wk : Wv))[e];
    const __nv_bfloat16 h = bsplit_hi(v);
    g_Wh[m * CC * CC + e] = h;
    g_Wl[m * CC * CC + e] = bsplit_lo(v, h);
}

// ---------------------------------------------------------------------------
// qkv_mma (unchanged, proven)
// ---------------------------------------------------------------------------
__global__ __launch_bounds__(256) void qkv_mma(
    const float* __restrict__ bq, const float* __restrict__ bk,
    const float* __restrict__ bv)
{
    extern __shared__ __align__(16) char sm[];
    const int n0 = blockIdx.x * 128;
    const int o0 = blockIdx.y * 64;
    const int b  = blockIdx.z;

    const int tid  = threadIdx.x;
    const int wid  = tid >> 5;
    const int lane = tid & 31;
    const int wn   = wid & 1;
    const int wm   = wid >> 1;

    const uint32_t smbase = smem_u32(sm);

    const __nv_bfloat16* gXh = g_Xh + ((size_t)b * NN + n0) * CC;
    const __nv_bfloat16* gXl = g_Xl + ((size_t)b * NN + n0) * CC;
    const __nv_bfloat16* W6[6] = {
        g_Wh,               g_Wl,
        g_Wh + CC * CC,     g_Wl + CC * CC,
        g_Wh + 2 * CC * CC, g_Wl + 2 * CC * CC };

    const uint32_t offA = (uint32_t)((lane & 15) * ROW_STRIDE + (lane >> 4) * 16);
    const uint32_t offB = (uint32_t)(((lane & 7) + ((lane >> 4) << 3)) * ROW_STRIDE
                                     + (((lane >> 3) & 1) << 4));

    float acc[3][2][4][4] = {};

    const int alr = tid >> 1, alc = (tid & 1) * 2;
    const int brb = tid >> 2, bcb = tid & 3;

    auto issue = [&](int buf, int k0) {
        const uint32_t base = smbase + buf * QBUF;
        #pragma unroll
        for (int c = 0; c < 2; c++) {
            const int chunk = alc + c;
            const uint32_t so = base + (uint32_t)(alr * ROW_STRIDE + chunk * 16);
            const size_t gofs = (size_t)alr * CC + k0 + chunk * 8;
            CP_ASYNC16(so,              gXh + gofs);
            CP_ASYNC16(so + TILE_BYTES, gXl + gofs);
        }
        const uint32_t sob = base + 2 * TILE_BYTES
                           + (uint32_t)(brb * ROW_STRIDE + bcb * 16);
        const size_t gwb = (size_t)(o0 + brb) * CC + k0 + bcb * 8;
        #pragma unroll
        for (int m = 0; m < 6; m++)
            CP_ASYNC16(sob + m * QB_TILE, W6[m] + gwb);
        CP_COMMIT();
    };

    issue(0, 0);
    issue(1, 32);

    #pragma unroll 1
    for (int t = 0; t < 8; t++) {
        if (t == 7) { CP_WAIT(0); } else { CP_WAIT(1); }
        __syncthreads();
        const uint32_t base = smbase + (t & 1) * QBUF;

        #pragma unroll
        for (int ks = 0; ks < 2; ks++) {
            const uint32_t kb2 = ks * 32;
            uint32_t ah[2][4], al[2][4];
            #pragma unroll
            for (int mt = 0; mt < 2; mt++) {
                const uint32_t toff = (uint32_t)((wm * 32 + mt * 16) * ROW_STRIDE) + kb2 + offA;
                LDSM_X4(ah[mt][0], ah[mt][1], ah[mt][2], ah[mt][3], base + toff);
                LDSM_X4(al[mt][0], al[mt][1], al[mt][2], al[mt][3], base + TILE_BYTES + toff);
            }
            #pragma unroll
            for (int q = 0; q < 3; q++) {
                uint32_t bh[4][2], bl[4][2];
                #pragma unroll
                for (int g = 0; g < 2; g++) {
                    const uint32_t toffb = (uint32_t)((wn * 32 + g * 16) * ROW_STRIDE) + kb2 + offB;
                    const uint32_t bbh = base + 2 * TILE_BYTES + (2 * q)     * QB_TILE + toffb;
                    const uint32_t bbl = base + 2 * TILE_BYTES + (2 * q + 1) * QB_TILE + toffb;
                    LDSM_X4(bh[2*g][0], bh[2*g][1], bh[2*g+1][0], bh[2*g+1][1], bbh);
                    LDSM_X4(bl[2*g][0], bl[2*g][1], bl[2*g+1][0], bl[2*g+1][1], bbl);
                }
                #pragma unroll
                for (int mt = 0; mt < 2; mt++)
                    #pragma unroll
                    for (int nt = 0; nt < 4; nt++) {
                        MMA16816(acc[q][mt][nt], ah[mt], bh[nt][0], bh[nt][1]);
                        MMA16816(acc[q][mt][nt], ah[mt], bl[nt][0], bl[nt][1]);
                        MMA16816(acc[q][mt][nt], al[mt], bh[nt][0], bh[nt][1]);
                    }
            }
        }
        __syncthreads();
        if (t + 2 < 8) issue(t & 1, (t + 2) * 32);
    }

    const int g  = lane >> 2;
    const int tq = lane & 3;

    #pragma unroll
    for (int mt = 0; mt < 2; mt++)
        #pragma unroll
        for (int h = 0; h < 2; h++) {
            const int n = n0 + wm * 32 + mt * 16 + g + h * 8;
            #pragma unroll
            for (int nt = 0; nt < 4; nt++) {
                const int col = o0 + wn * 32 + nt * 8 + tq * 2;
                const size_t idx = ((size_t)b * NN + n) * CC + col;
                const float q0 = acc[0][mt][nt][2*h]   + bq[col];
                const float q1 = acc[0][mt][nt][2*h+1] + bq[col + 1];
                const float k0v = acc[1][mt][nt][2*h]   + bk[col];
                const float k1v = acc[1][mt][nt][2*h+1] + bk[col + 1];
                const __nv_bfloat16 qh0 = bsplit_hi(q0), qh1 = bsplit_hi(q1);
                const __nv_bfloat16 kh0 = bsplit_hi(k0v), kh1 = bsplit_hi(k1v);
                *(__nv_bfloat162*)&g_Qh[idx] = __halves2bfloat162(qh0, qh1);
                *(__nv_bfloat162*)&g_Ql[idx] = __halves2bfloat162(bsplit_lo(q0, qh0), bsplit_lo(q1, qh1));
                *(__nv_bfloat162*)&g_Kh[idx] = __halves2bfloat162(kh0, kh1);
                *(__nv_bfloat162*)&g_Kl[idx] = __halves2bfloat162(bsplit_lo(k0v, kh0), bsplit_lo(k1v, kh1));
            }
        }

    __syncthreads();
    float* vbuf = (float*)sm;
    #pragma unroll
    for (int mt = 0; mt < 2; mt++)
        #pragma unroll
        for (int h = 0; h < 2; h++) {
            const int row = wm * 32 + mt * 16 + g + h * 8;
            #pragma unroll
            for (int nt = 0; nt < 4; nt++) {
                const int col = wn * 32 + nt * 8 + tq * 2;
                vbuf[row * 65 + col]     = acc[2][mt][nt][2*h]   + bv[o0 + col];
                vbuf[row * 65 + col + 1] = acc[2][mt][nt][2*h+1] + bv[o0 + col + 1];
            }
        }
    __syncthreads();
    #pragma unroll
    for (int cr = 0; cr < 8; cr++) {
        const int c = wid * 8 + cr;
        const size_t obase = ((size_t)b * CC + o0 + c) * NN + n0;
        #pragma unroll
        for (int it = 0; it < 2; it++) {
            const int nl = it * 64 + lane * 2;
            const float f0 = vbuf[nl * 65 + c];
            const float f1 = vbuf[(nl + 1) * 65 + c];
            const __nv_bfloat16 h0 = bsplit_hi(f0), h1 = bsplit_hi(f1);
            *(__nv_bfloat162*)&g_Vh[obase + nl] = __halves2bfloat162(h0, h1);
            *(__nv_bfloat162*)&g_Vl[obase + nl] = __halves2bfloat162(bsplit_lo(f0, h0), bsplit_lo(f1, h1));
        }
    }
}

// ---------------------------------------------------------------------------
// flash_kernel: fused scores + softmax + P.V + residual.
// CTA = (batch b, 64-row Q tile). 256 threads, 8 warps.
// S phase: warp = 16 rows x 64 cols.  PV phase: warp = 16 rows x 128 c.
// ---------------------------------------------------------------------------
__global__ __launch_bounds__(256, 1) void flash_kernel(
    const float* __restrict__ x, float* __restrict__ out)
{
    extern __shared__ __align__(16) char sm[];
    const uint32_t base = smem_u32(sm);
    const int n0 = blockIdx.x * 64;
    const int b  = blockIdx.y;

    const int tid  = threadIdx.x;
    const int wid  = tid >> 5;
    const int lane = tid & 31;
    const int wm   = wid >> 1;      // 0..3 (rows)
    const int wn   = wid & 1;       // 0..1 (cols)
    const int g    = lane >> 2;
    const int tq   = lane & 3;

    const __nv_bfloat16* Qhp = g_Qh + ((size_t)b * NN + n0) * CC;
    const __nv_bfloat16* Qlp = g_Ql + ((size_t)b * NN + n0) * CC;
    const __nv_bfloat16* Khp = g_Kh + (size_t)b * NN * CC;
    const __nv_bfloat16* Klp = g_Kl + (size_t)b * NN * CC;
    const __nv_bfloat16* Vhp = g_Vh + (size_t)b * CC * NN;
    const __nv_bfloat16* Vlp = g_Vl + (size_t)b * CC * NN;

    // ---- load Q tile (8 chunks of 64 rows x 32 cols, hi+lo) ----
    {
        const int lr = tid >> 2, ls = tid & 3;
        #pragma unroll
        for (int ck = 0; ck < 8; ck++) {
            const uint32_t so = base + F_QH + ck * 5120 + lr * ROW_STRIDE + ls * 16;
            const size_t go = (size_t)lr * CC + ck * 32 + ls * 8;
            CP_ASYNC16(so, Qhp + go);
            CP_ASYNC16(so + (F_QL - F_QH), Qlp + go);
        }
        CP_COMMIT();
    }

    const uint32_t offA = (uint32_t)((lane & 15) * ROW_STRIDE + (lane >> 4) * 16);
    const uint32_t offB = (uint32_t)(((lane & 7) + ((lane >> 4) << 3)) * ROW_STRIDE
                                     + (((lane >> 3) & 1) << 4));

    float m0 = -1e30f, m1 = -1e30f, l0 = 0.f, l1 = 0.f;
    float acc_o[16][4];
    #pragma unroll
    for (int i = 0; i < 16; i++)
        #pragma unroll
        for (int r = 0; r < 4; r++) acc_o[i][r] = 0.f;

    const int lr4 = tid >> 2, ls4 = tid & 3;

    auto issueK = [&](int buf, int mt, int ck) {
        const uint32_t sb = base + F_STR + buf * 20480;
        #pragma unroll
        for (int rr = 0; rr < 2; rr++) {
            const int row = lr4 + rr * 64;
            const uint32_t so = sb + row * ROW_STRIDE + ls4 * 16;
            const size_t go = (size_t)(mt * 128 + row) * CC + ck * 32 + ls4 * 8;
            CP_ASYNC16(so,          Khp + go);
            CP_ASYNC16(so + 10240,  Klp + go);
        }
        CP_COMMIT();
    };
    auto issueV = [&](int buf, int mt, int vk) {
        const uint32_t sb = base + F_STR + buf * 40960;
        #pragma unroll
        for (int rr = 0; rr < 4; rr++) {
            const int row = lr4 + rr * 64;
            const uint32_t so = sb + row * ROW_STRIDE + ls4 * 16;
            const size_t go = (size_t)row * NN + mt * 128 + vk * 32 + ls4 * 8;
            CP_ASYNC16(so,          Vhp + go);
            CP_ASYNC16(so + 20480,  Vlp + go);
        }
        CP_COMMIT();
    };

    float* redm = (float*)(sm + F_RED);
    float* reds = (float*)(sm + F_RED + 512);
    const int row0 = wm * 16 + g;
    const int row1 = row0 + 8;

    #pragma unroll 1
    for (int mt = 0; mt < 16; mt++) {
        // ================= S = Q . K^T  (64 x 128) =================
        float acc_s[8][4];
        #pragma unroll
        for (int i = 0; i < 8; i++)
            #pragma unroll
            for (int r = 0; r < 4; r++) acc_s[i][r] = 0.f;

        issueK(0, mt, 0);
        #pragma unroll 1
        for (int ck = 0; ck < 8; ck++) {
            CP_WAIT(0);
            __syncthreads();
            if (ck < 7) issueK((ck + 1) & 1, mt, ck + 1);
            const uint32_t aK = base + F_STR + (ck & 1) * 20480;
            const uint32_t aQ = base + F_QH + ck * 5120;
            #pragma unroll
            for (int kk = 0; kk < 2; kk++) {
                const uint32_t kb2 = kk * 32;
                uint32_t ah[4], al[4];
                const uint32_t ta = aQ + (wm * 16) * ROW_STRIDE + kb2 + offA;
                LDSM_X4(ah[0], ah[1], ah[2], ah[3], ta);
                LDSM_X4(al[0], al[1], al[2], al[3], ta + (F_QL - F_QH));
                #pragma unroll
                for (int gB = 0; gB < 4; gB++) {
                    uint32_t bh[4], bl[4];
                    const uint32_t tb = aK + (wn * 64 + gB * 16) * ROW_STRIDE + kb2 + offB;
                    LDSM_X4(bh[0], bh[1], bh[2], bh[3], tb);
                    LDSM_X4(bl[0], bl[1], bl[2], bl[3], tb + 10240);
                    MMA16816(acc_s[2*gB],   ah, bh[0], bh[1]);
                    MMA16816(acc_s[2*gB+1], ah, bh[2], bh[3]);
                    MMA16816(acc_s[2*gB],   ah, bl[0], bl[1]);
                    MMA16816(acc_s[2*gB+1], ah, bl[2], bl[3]);
                    MMA16816(acc_s[2*gB],   al, bh[0], bh[1]);
                    MMA16816(acc_s[2*gB+1], al, bh[2], bh[3]);
                }
            }
        }

        // ================= online softmax =================
        const float scale = 1.0f / 16.0f;
        float pm0 = -1e30f, pm1 = -1e30f;
        #pragma unroll
        for (int nt = 0; nt < 8; nt++) {
            acc_s[nt][0] *= scale; acc_s[nt][1] *= scale;
            acc_s[nt][2] *= scale; acc_s[nt][3] *= scale;
            pm0 = fmaxf(pm0, fmaxf(acc_s[nt][0], acc_s[nt][1]));
            pm1 = fmaxf(pm1, fmaxf(acc_s[nt][2], acc_s[nt][3]));
        }
        pm0 = fmaxf(pm0, __shfl_xor_sync(0xffffffffu, pm0, 1));
        pm0 = fmaxf(pm0, __shfl_xor_sync(0xffffffffu, pm0, 2));
        pm1 = fmaxf(pm1, __shfl_xor_sync(0xffffffffu, pm1, 1));
        pm1 = fmaxf(pm1, __shfl_xor_sync(0xffffffffu, pm1, 2));
        if (tq == 0) { redm[row0 * 2 + wn] = pm0; redm[row1 * 2 + wn] = pm1; }
        __syncthreads();
        const float nm0 = fmaxf(m0, fmaxf(redm[row0 * 2], redm[row0 * 2 + 1]));
        const float nm1 = fmaxf(m1, fmaxf(redm[row1 * 2], redm[row1 * 2 + 1]));
        const float a0 = __expf(m0 - nm0);
        const float a1 = __expf(m1 - nm1);

        float ps0 = 0.f, ps1 = 0.f;
        #pragma unroll
        for (int nt = 0; nt < 8; nt++) {
            acc_s[nt][0] = __expf(acc_s[nt][0] - nm0);
            acc_s[nt][1] = __expf(acc_s[nt][1] - nm0);
            acc_s[nt][2] = __expf(acc_s[nt][2] - nm1);
            acc_s[nt][3] = __expf(acc_s[nt][3] - nm1);
            ps0 += acc_s[nt][0] + acc_s[nt][1];
            ps1 += acc_s[nt][2] + acc_s[nt][3];
        }
        ps0 += __shfl_xor_sync(0xffffffffu, ps0, 1);
        ps0 += __shfl_xor_sync(0xffffffffu, ps0, 2);
        ps1 += __shfl_xor_sync(0xffffffffu, ps1, 1);
        ps1 += __shfl_xor_sync(0xffffffffu, ps1, 2);

        // store P (bf16 hi/lo) to smem chunk tiles
        #pragma unroll
        for (int nt = 0; nt < 8; nt++) {
            const int col = wn * 64 + nt * 8 + tq * 2;
            const int pc = col >> 5, c32 = col & 31;
            const uint32_t o0b = F_PH + pc * 5120 + c32 * 2;
            const float p0 = acc_s[nt][0], p1 = acc_s[nt][1];
            const float p2 = acc_s[nt][2], p3 = acc_s[nt][3];
            const __nv_bfloat16 h0 = bsplit_hi(p0), h1 = bsplit_hi(p1);
            const __nv_bfloat16 h2 = bsplit_hi(p2), h3 = bsplit_hi(p3);
            *(__nv_bfloat162*)(sm + o0b + row0 * ROW_STRIDE) = __halves2bfloat162(h0, h1);
            *(__nv_bfloat162*)(sm + o0b + row1 * ROW_STRIDE) = __halves2bfloat162(h2, h3);
            *(__nv_bfloat162*)(sm + o0b + (F_PL - F_PH) + row0 * ROW_STRIDE)
                = __halves2bfloat162(bsplit_lo(p0, h0), bsplit_lo(p1, h1));
            *(__nv_bfloat162*)(sm + o0b + (F_PL - F_PH) + row1 * ROW_STRIDE)
                = __halves2bfloat162(bsplit_lo(p2, h2), bsplit_lo(p3, h3));
        }
        if (tq == 0) { reds[row0 * 2 + wn] = ps0; reds[row1 * 2 + wn] = ps1; }
        __syncthreads();   // P visible + sums ready
        l0 = l0 * a0 + reds[row0 * 2] + reds[row0 * 2 + 1];
        l1 = l1 * a1 + reds[row1 * 2] + reds[row1 * 2 + 1];
        m0 = nm0; m1 = nm1;
        #pragma unroll
        for (int nt = 0; nt < 16; nt++) {
            acc_o[nt][0] *= a0; acc_o[nt][1] *= a0;
            acc_o[nt][2] *= a1; acc_o[nt][3] *= a1;
        }

        // ================= O += P . V^T  (64 x 256) =================
        issueV(0, mt, 0);
        #pragma unroll 1
        for (int vk = 0; vk < 4; vk++) {
            CP_WAIT(0);
            __syncthreads();
            if (vk < 3) issueV((vk + 1) & 1, mt, vk + 1);
            const uint32_t aV = base + F_STR + (vk & 1) * 40960;
            const uint32_t aP = base + F_PH + vk * 5120;
            #pragma unroll
            for (int kk = 0; kk < 2; kk++) {
                const uint32_t kb2 = kk * 32;
                uint32_t ah[4], al[4];
                const uint32_t ta = aP + (wm * 16) * ROW_STRIDE + kb2 + offA;
                LDSM_X4(ah[0], ah[1], ah[2], ah[3], ta);
                LDSM_X4(al[0], al[1], al[2], al[3], ta + (F_PL - F_PH));
                #pragma unroll
                for (int gB = 0; gB < 8; gB++) {
                    uint32_t bh[4], bl[4];
                    const uint32_t tb = aV + (wn * 128 + gB * 16) * ROW_STRIDE + kb2 + offB;
                    LDSM_X4(bh[0], bh[1], bh[2], bh[3], tb);
                    LDSM_X4(bl[0], bl[1], bl[2], bl[3], tb + 20480);
                    MMA16816(acc_o[2*gB],   ah, bh[0], bh[1]);
                    MMA16816(acc_o[2*gB+1], ah, bh[2], bh[3]);
                    MMA16816(acc_o[2*gB],   al, bh[0], bh[1]);
                    MMA16816(acc_o[2*gB+1], al, bh[2], bh[3]);
                    MMA16816(acc_o[2*gB],   ah, bl[0], bl[1]);
                    MMA16816(acc_o[2*gB+1], ah, bl[2], bl[3]);
                }
            }
        }
    }

    // ================= epilogue: O/l, transpose, +x =================
    __syncthreads();
    float* stage = (float*)(sm + F_STR);     // [64][261]
    const float i0v = 1.0f / l0, i1v = 1.0f / l1;
    #pragma unroll
    for (int nt = 0; nt < 16; nt++) {
        const int col = wn * 128 + nt * 8 + tq * 2;
        stage[row0 * 261 + col]     = acc_o[nt][0] * i0v;
        stage[row0 * 261 + col + 1] = acc_o[nt][1] * i0v;
        stage[row1 * 261 + col]     = acc_o[nt][2] * i1v;
        stage[row1 * 261 + col + 1] = acc_o[nt][3] * i1v;
    }
    __syncthreads();
    #pragma unroll 1
    for (int cr = 0; cr < 32; cr++) {
        const int c = wid * 32 + cr;
        const float* xr = x   + ((size_t)b * CC + c) * NN + n0;
        float*       orw = out + ((size_t)b * CC + c) * NN + n0;
        orw[lane]      = stage[lane * 261 + c]        + xr[lane];
        orw[lane + 32] = stage[(lane + 32) * 261 + c] + xr[lane + 32];
    }
}

// ---------------------------------------------------------------------------
extern "C" void kernel_launch(void* const* d_in, const int* in_sizes, int n_in,
                              void* d_out, int out_size)
{
    const float* x  = (const float*)d_in[0];
    const float* Wq = (const float*)d_in[1];
    const float* bq = (const float*)d_in[2];
    const float* Wk = (const float*)d_in[3];
    const float* bk = (const float*)d_in[4];
    const float* Wv = (const float*)d_in[5];
    const float* bv = (const float*)d_in[6];
    float* out = (float*)d_out;

    cudaFuncSetAttribute(qkv_mma,
                         cudaFuncAttributeMaxDynamicSharedMemorySize, QSMEM);
    cudaFuncSetAttribute(flash_kernel,
                         cudaFuncAttributeMaxDynamicSharedMemorySize, F_SMEM);

    dim3 blk(256);
    xsplit_kernel<<<dim3(NN / 32, CC / 32, BB), blk>>>(x);
    wsplit_kernel<<<dim3(CC, 3), blk>>>(Wq, Wk, Wv);
    qkv_mma<<<dim3(NN / 128, CC / 64, BB), blk, QSMEM>>>(bq, bk, bv);
    flash_kernel<<<dim3(NN / 64, BB), blk, F_SMEM>>>(x, out);
}

// round 7
// speedup vs baseline: 1.9050x; 1.9050x over previous
#include <cuda_runtime.h>
#include <cuda_bf16.h>
#include <cstdint>

#define BB 8
#define CC 256
#define NN 2048

// ---------------- scratch (device globals; no allocs) ----------------------
__device__ __nv_bfloat16 g_Xh[BB * NN * CC], g_Xl[BB * NN * CC];   // xT [b][n][c]
__device__ __nv_bfloat16 g_Wh[3 * CC * CC],  g_Wl[3 * CC * CC];    // Wq,Wk,Wv split
__device__ __nv_bfloat16 g_Qh[BB * NN * CC];                       // [b][n][c]
__device__ __nv_bfloat16 g_Kh[BB * NN * CC];                       // [b][m][c]
__device__ __nv_bfloat16 g_Vh[BB * CC * NN];                       // [b][c][m]
__device__ float         g_S [(size_t)BB * NN * NN];               // fp32 scores
__device__ __nv_bfloat16 g_Ph[(size_t)BB * NN * NN];               // probs (bf16)

// ---------------- PTX helpers (baseline PTX only) ---------------------------
__device__ __forceinline__ uint32_t smem_u32(const void* p) {
    uint32_t a;
    asm("{ .reg .u64 t; cvta.to.shared.u64 t, %1; cvt.u32.u64 %0, t; }"
        : "=r"(a) : "l"(p));
    return a;
}

#define CP_ASYNC16(dst, src) \
    asm volatile("cp.async.cg.shared.global [%0], [%1], 16;" \
                 :: "r"(dst), "l"(src) : "memory")
#define CP_COMMIT() asm volatile("cp.async.commit_group;" ::: "memory")
#define CP_WAIT(n)  asm volatile("cp.async.wait_group %0;" :: "n"(n) : "memory")

#define LDSM_X4(r0, r1, r2, r3, addr) \
    asm volatile("ldmatrix.sync.aligned.m8n8.x4.shared.b16 {%0,%1,%2,%3}, [%4];" \
                 : "=r"(r0), "=r"(r1), "=r"(r2), "=r"(r3) : "r"(addr))

#define MMA16816(c, a, b0, b1) \
    asm volatile("mma.sync.aligned.m16n8k16.row.col.f32.bf16.bf16.f32 " \
                 "{%0,%1,%2,%3}, {%4,%5,%6,%7}, {%8,%9}, {%0,%1,%2,%3};" \
                 : "+f"((c)[0]), "+f"((c)[1]), "+f"((c)[2]), "+f"((c)[3]) \
                 : "r"((a)[0]), "r"((a)[1]), "r"((a)[2]), "r"((a)[3]), \
                   "r"(b0), "r"(b1))

__device__ __forceinline__ __nv_bfloat16 bsplit_hi(float v) { return __float2bfloat16(v); }
__device__ __forceinline__ __nv_bfloat16 bsplit_lo(float v, __nv_bfloat16 h) {
    return __float2bfloat16(v - __bfloat162float(h));
}

#define ROW_STRIDE 80
#define TILE_BYTES 10240            // 128 rows * 80 B
// single-pass gemm: 3-stage ring, each stage = A tile + B tile
#define S_STAGE    (2 * TILE_BYTES)         // 20480
#define G_SMEM     (3 * S_STAGE)            // 61440
// qkv kernel smem (3-pass, unchanged)
#define QB_TILE    5120
#define QBUF       (2 * TILE_BYTES + 6 * QB_TILE)   // 51200
#define QSMEM      (2 * QBUF)                       // 102400

// ---------------------------------------------------------------------------
// xsplit: x [b][c][n] fp32 -> xT hi/lo [b][n][c] bf16
// ---------------------------------------------------------------------------
__global__ __launch_bounds__(256) void xsplit_kernel(const float* __restrict__ x)
{
    __shared__ float t[32][33];
    const int n0 = blockIdx.x * 32;
    const int c0 = blockIdx.y * 32;
    const int b  = blockIdx.z;
    const int tx = threadIdx.x & 31;
    const int ty = threadIdx.x >> 5;

    #pragma unroll
    for (int k = 0; k < 4; k++)
        t[ty + k * 8][tx] = x[((size_t)b * CC + c0 + ty + k * 8) * NN + n0 + tx];
    __syncthreads();
    #pragma unroll
    for (int k = 0; k < 4; k++) {
        const float v = t[tx][ty + k * 8];
        const __nv_bfloat16 h = bsplit_hi(v);
        const size_t idx = ((size_t)b * NN + n0 + ty + k * 8) * CC + c0 + tx;
        g_Xh[idx] = h;
        g_Xl[idx] = bsplit_lo(v, h);
    }
}

// ---------------------------------------------------------------------------
// wsplit
// ---------------------------------------------------------------------------
__global__ __launch_bounds__(256) void wsplit_kernel(
    const float* __restrict__ Wq, const float* __restrict__ Wk,
    const float* __restrict__ Wv)
{
    const int m = blockIdx.y;
    const int e = blockIdx.x * 256 + threadIdx.x;
    const float v = (m == 0 ? Wq : (m == 1 ? Wk : Wv))[e];
    const __nv_bfloat16 h = bsplit_hi(v);
    g_Wh[m * CC * CC + e] = h;
    g_Wl[m * CC * CC + e] = bsplit_lo(v, h);
}

// ---------------------------------------------------------------------------
// qkv_mma: 3-pass HMMA projection (proven). Epilogue stores hi only.
// ---------------------------------------------------------------------------
__global__ __launch_bounds__(256) void qkv_mma(
    const float* __restrict__ bq, const float* __restrict__ bk,
    const float* __restrict__ bv)
{
    extern __shared__ __align__(16) char sm[];
    const int n0 = blockIdx.x * 128;
    const int o0 = blockIdx.y * 64;
    const int b  = blockIdx.z;

    const int tid  = threadIdx.x;
    const int wid  = tid >> 5;
    const int lane = tid & 31;
    const int wn   = wid & 1;
    const int wm   = wid >> 1;

    const uint32_t smbase = smem_u32(sm);

    const __nv_bfloat16* gXh = g_Xh + ((size_t)b * NN + n0) * CC;
    const __nv_bfloat16* gXl = g_Xl + ((size_t)b * NN + n0) * CC;
    const __nv_bfloat16* W6[6] = {
        g_Wh,               g_Wl,
        g_Wh + CC * CC,     g_Wl + CC * CC,
        g_Wh + 2 * CC * CC, g_Wl + 2 * CC * CC };

    const uint32_t offA = (uint32_t)((lane & 15) * ROW_STRIDE + (lane >> 4) * 16);
    const uint32_t offB = (uint32_t)(((lane & 7) + ((lane >> 4) << 3)) * ROW_STRIDE
                                     + (((lane >> 3) & 1) << 4));

    float acc[3][2][4][4] = {};

    const int alr = tid >> 1, alc = (tid & 1) * 2;
    const int brb = tid >> 2, bcb = tid & 3;

    auto issue = [&](int buf, int k0) {
        const uint32_t base = smbase + buf * QBUF;
        #pragma unroll
        for (int c = 0; c < 2; c++) {
            const int chunk = alc + c;
            const uint32_t so = base + (uint32_t)(alr * ROW_STRIDE + chunk * 16);
            const size_t gofs = (size_t)alr * CC + k0 + chunk * 8;
            CP_ASYNC16(so,              gXh + gofs);
            CP_ASYNC16(so + TILE_BYTES, gXl + gofs);
        }
        const uint32_t sob = base + 2 * TILE_BYTES
                           + (uint32_t)(brb * ROW_STRIDE + bcb * 16);
        const size_t gwb = (size_t)(o0 + brb) * CC + k0 + bcb * 8;
        #pragma unroll
        for (int m = 0; m < 6; m++)
            CP_ASYNC16(sob + m * QB_TILE, W6[m] + gwb);
        CP_COMMIT();
    };

    issue(0, 0);
    issue(1, 32);

    #pragma unroll 1
    for (int t = 0; t < 8; t++) {
        if (t == 7) { CP_WAIT(0); } else { CP_WAIT(1); }
        __syncthreads();
        const uint32_t base = smbase + (t & 1) * QBUF;

        #pragma unroll
        for (int ks = 0; ks < 2; ks++) {
            const uint32_t kb2 = ks * 32;
            uint32_t ah[2][4], al[2][4];
            #pragma unroll
            for (int mt = 0; mt < 2; mt++) {
                const uint32_t toff = (uint32_t)((wm * 32 + mt * 16) * ROW_STRIDE) + kb2 + offA;
                LDSM_X4(ah[mt][0], ah[mt][1], ah[mt][2], ah[mt][3], base + toff);
                LDSM_X4(al[mt][0], al[mt][1], al[mt][2], al[mt][3], base + TILE_BYTES + toff);
            }
            #pragma unroll
            for (int q = 0; q < 3; q++) {
                uint32_t bh[4][2], bl[4][2];
                #pragma unroll
                for (int g = 0; g < 2; g++) {
                    const uint32_t toffb = (uint32_t)((wn * 32 + g * 16) * ROW_STRIDE) + kb2 + offB;
                    const uint32_t bbh = base + 2 * TILE_BYTES + (2 * q)     * QB_TILE + toffb;
                    const uint32_t bbl = base + 2 * TILE_BYTES + (2 * q + 1) * QB_TILE + toffb;
                    LDSM_X4(bh[2*g][0], bh[2*g][1], bh[2*g+1][0], bh[2*g+1][1], bbh);
                    LDSM_X4(bl[2*g][0], bl[2*g][1], bl[2*g+1][0], bl[2*g+1][1], bbl);
                }
                #pragma unroll
                for (int mt = 0; mt < 2; mt++)
                    #pragma unroll
                    for (int nt = 0; nt < 4; nt++) {
                        MMA16816(acc[q][mt][nt], ah[mt], bh[nt][0], bh[nt][1]);
                        MMA16816(acc[q][mt][nt], ah[mt], bl[nt][0], bl[nt][1]);
                        MMA16816(acc[q][mt][nt], al[mt], bh[nt][0], bh[nt][1]);
                    }
            }
        }
        __syncthreads();
        if (t + 2 < 8) issue(t & 1, (t + 2) * 32);
    }

    const int g  = lane >> 2;
    const int tq = lane & 3;

    // Q, K hi-only stores
    #pragma unroll
    for (int mt = 0; mt < 2; mt++)
        #pragma unroll
        for (int h = 0; h < 2; h++) {
            const int n = n0 + wm * 32 + mt * 16 + g + h * 8;
            #pragma unroll
            for (int nt = 0; nt < 4; nt++) {
                const int col = o0 + wn * 32 + nt * 8 + tq * 2;
                const size_t idx = ((size_t)b * NN + n) * CC + col;
                const float q0 = acc[0][mt][nt][2*h]   + bq[col];
                const float q1 = acc[0][mt][nt][2*h+1] + bq[col + 1];
                const float k0v = acc[1][mt][nt][2*h]   + bk[col];
                const float k1v = acc[1][mt][nt][2*h+1] + bk[col + 1];
                *(__nv_bfloat162*)&g_Qh[idx] = __halves2bfloat162(bsplit_hi(q0), bsplit_hi(q1));
                *(__nv_bfloat162*)&g_Kh[idx] = __halves2bfloat162(bsplit_hi(k0v), bsplit_hi(k1v));
            }
        }

    // V: stage fp32 in smem, transpose to [c][n], store hi only
    __syncthreads();
    float* vbuf = (float*)sm;
    #pragma unroll
    for (int mt = 0; mt < 2; mt++)
        #pragma unroll
        for (int h = 0; h < 2; h++) {
            const int row = wm * 32 + mt * 16 + g + h * 8;
            #pragma unroll
            for (int nt = 0; nt < 4; nt++) {
                const int col = wn * 32 + nt * 8 + tq * 2;
                vbuf[row * 65 + col]     = acc[2][mt][nt][2*h]   + bv[o0 + col];
                vbuf[row * 65 + col + 1] = acc[2][mt][nt][2*h+1] + bv[o0 + col + 1];
            }
        }
    __syncthreads();
    #pragma unroll
    for (int cr = 0; cr < 8; cr++) {
        const int c = wid * 8 + cr;
        const size_t obase = ((size_t)b * CC + o0 + c) * NN + n0;
        #pragma unroll
        for (int it = 0; it < 2; it++) {
            const int nl = it * 64 + lane * 2;
            const float f0 = vbuf[nl * 65 + c];
            const float f1 = vbuf[(nl + 1) * 65 + c];
            *(__nv_bfloat162*)&g_Vh[obase + nl]
                = __halves2bfloat162(bsplit_hi(f0), bsplit_hi(f1));
        }
    }
}

// ---------------------------------------------------------------------------
// Single-pass bf16 NT GEMM, 3-stage cp.async ring, ONE barrier per K-tile.
//   C[i][j] = s * sum_k A[i][k]*B[j][k]  (+ R[i][j])
// 128x128 tile, 256 thr (8 warps 2x4), warp 64x32, BK=32.
// ---------------------------------------------------------------------------
template<int KTILES, bool SCALE, bool RESID>
__global__ __launch_bounds__(256, 2) void mma_gemm(
    const __nv_bfloat16* __restrict__ A, const __nv_bfloat16* __restrict__ B,
    float* __restrict__ C, const float* __restrict__ R,
    int lda, int ldb, int ldc, float scale,
    size_t sA, size_t sB, size_t sC)
{
    extern __shared__ __align__(16) char sm[];

    const int j0 = blockIdx.x * 128;
    const int i0 = blockIdx.y * 128;
    const int b  = blockIdx.z;

    const int tid  = threadIdx.x;
    const int lane = tid & 31;
    const int wid  = tid >> 5;
    const int wm   = wid >> 2;
    const int wn   = wid & 3;

    const __nv_bfloat16* gA = A + (size_t)b * sA;
    const __nv_bfloat16* gB = B + (size_t)b * sB;

    const int lr = tid >> 1;
    const int lc = (tid & 1) * 2;
    const uint32_t smbase = smem_u32(sm);

    const uint32_t offA = (uint32_t)((lane & 15) * ROW_STRIDE + (lane >> 4) * 16);
    const uint32_t offB = (uint32_t)(((lane & 7) + ((lane >> 4) << 3)) * ROW_STRIDE
                                     + (((lane >> 3) & 1) << 4));

    float acc[4][4][4] = {};

    auto issue = [&](int buf, int k0) {
        const uint32_t base = smbase + buf * S_STAGE;
        #pragma unroll
        for (int c = 0; c < 2; c++) {
            const int chunk = lc + c;
            const uint32_t so = base + (uint32_t)(lr * ROW_STRIDE + chunk * 16);
            CP_ASYNC16(so,              gA + (size_t)(i0 + lr) * lda + k0 + chunk * 8);
            CP_ASYNC16(so + TILE_BYTES, gB + (size_t)(j0 + lr) * ldb + k0 + chunk * 8);
        }
        CP_COMMIT();
    };

    issue(0, 0);
    issue(1, 32);

    int buf = 0;
    #pragma unroll 1
    for (int t = 0; t < KTILES; t++) {
        if (t == KTILES - 1) { CP_WAIT(0); } else { CP_WAIT(1); }
        __syncthreads();
        if (t + 2 < KTILES) {
            int pb = buf + 2; if (pb >= 3) pb -= 3;
            issue(pb, (t + 2) * 32);
        }

        const uint32_t aA = smbase + buf * S_STAGE;
        const uint32_t aB = aA + TILE_BYTES;

        #pragma unroll
        for (int ks = 0; ks < 2; ks++) {
            const uint32_t kb2 = ks * 32;
            uint32_t ahf[4][4];
            #pragma unroll
            for (int mt = 0; mt < 4; mt++) {
                const uint32_t toff = (uint32_t)((wm * 64 + mt * 16) * ROW_STRIDE) + kb2 + offA;
                LDSM_X4(ahf[mt][0], ahf[mt][1], ahf[mt][2], ahf[mt][3], aA + toff);
            }
            uint32_t bhf[4][2];
            #pragma unroll
            for (int g = 0; g < 2; g++) {
                const uint32_t toff = (uint32_t)((wn * 32 + g * 16) * ROW_STRIDE) + kb2 + offB;
                LDSM_X4(bhf[2*g][0], bhf[2*g][1], bhf[2*g+1][0], bhf[2*g+1][1], aB + toff);
            }
            #pragma unroll
            for (int mt = 0; mt < 4; mt++)
                #pragma unroll
                for (int nt = 0; nt < 4; nt++)
                    MMA16816(acc[mt][nt], ahf[mt], bhf[nt][0], bhf[nt][1]);
        }

        buf = (buf + 1 == 3) ? 0 : buf + 1;
    }

    const int g  = lane >> 2;
    const int tq = lane & 3;
    float* Cb = C + (size_t)b * sC;
    const float* Rb = R + (size_t)b * sC;

    #pragma unroll
    for (int mt = 0; mt < 4; mt++) {
        const int row0 = i0 + wm * 64 + mt * 16 + g;
        #pragma unroll
        for (int nt = 0; nt < 4; nt++) {
            const int col = j0 + wn * 32 + nt * 8 + tq * 2;
            float2 v0 = make_float2(acc[mt][nt][0], acc[mt][nt][1]);
            float2 v1 = make_float2(acc[mt][nt][2], acc[mt][nt][3]);
            if (SCALE) { v0.x *= scale; v0.y *= scale; v1.x *= scale; v1.y *= scale; }
            const size_t idx0 = (size_t)row0 * ldc + col;
            const size_t idx1 = (size_t)(row0 + 8) * ldc + col;
            if (RESID) {
                float2 r0 = *(const float2*)&Rb[idx0];
                float2 r1 = *(const float2*)&Rb[idx1];
                v0.x += r0.x; v0.y += r0.y; v1.x += r1.x; v1.y += r1.y;
            }
            *(float2*)&Cb[idx0] = v0;
            *(float2*)&Cb[idx1] = v1;
        }
    }
}

// ---------------------------------------------------------------------------
// softmax: fp32 scores -> bf16 probs (hi only).
// ---------------------------------------------------------------------------
__global__ __launch_bounds__(256) void softmax_kernel()
{
    __shared__ float redmax[8];
    __shared__ float redsum[8];

    const size_t row = blockIdx.x;
    const float* p = g_S + row * NN;
    __nv_bfloat16* ph = g_Ph + row * NN;
    const int tid  = threadIdx.x;
    const int lane = tid & 31;
    const int warp = tid >> 5;

    float v[8];
    float mx = -3.4e38f;
    #pragma unroll
    for (int t = 0; t < 8; t++) {
        v[t] = p[tid + t * 256];
        mx = fmaxf(mx, v[t]);
    }
    #pragma unroll
    for (int o = 16; o > 0; o >>= 1)
        mx = fmaxf(mx, __shfl_xor_sync(0xffffffffu, mx, o));
    if (lane == 0) redmax[warp] = mx;
    __syncthreads();
    if (warp == 0) {
        float w = (lane < 8) ? redmax[lane] : -3.4e38f;
        #pragma unroll
        for (int o = 4; o > 0; o >>= 1)
            w = fmaxf(w, __shfl_xor_sync(0xffffffffu, w, o));
        if (lane == 0) redmax[0] = w;
    }
    __syncthreads();
    mx = redmax[0];

    float s = 0.0f;
    #pragma unroll
    for (int t = 0; t < 8; t++) {
        v[t] = __expf(v[t] - mx);
        s += v[t];
    }
    #pragma unroll
    for (int o = 16; o > 0; o >>= 1)
        s += __shfl_xor_sync(0xffffffffu, s, o);
    if (lane == 0) redsum[warp] = s;
    __syncthreads();
    if (warp == 0) {
        float w = (lane < 8) ? redsum[lane] : 0.0f;
        #pragma unroll
        for (int o = 4; o > 0; o >>= 1)
            w += __shfl_xor_sync(0xffffffffu, w, o);
        if (lane == 0) redsum[0] = w;
    }
    __syncthreads();
    const float inv = 1.0f / redsum[0];

    #pragma unroll
    for (int t = 0; t < 8; t++)
        ph[tid + t * 256] = bsplit_hi(v[t] * inv);
}

// ---------------------------------------------------------------------------
extern "C" void kernel_launch(void* const* d_in, const int* in_sizes, int n_in,
                              void* d_out, int out_size)
{
    const float* x  = (const float*)d_in[0];
    const float* Wq = (const float*)d_in[1];
    const float* bq = (const float*)d_in[2];
    const float* Wk = (const float*)d_in[3];
    const float* bk = (const float*)d_in[4];
    const float* Wv = (const float*)d_in[5];
    const float* bv = (const float*)d_in[6];
    float* out = (float*)d_out;

    void *pQh, *pKh, *pVh, *pS, *pPh;
    cudaGetSymbolAddress(&pQh, g_Qh);
    cudaGetSymbolAddress(&pKh, g_Kh);
    cudaGetSymbolAddress(&pVh, g_Vh);
    cudaGetSymbolAddress(&pS,  g_S);
    cudaGetSymbolAddress(&pPh, g_Ph);

    cudaFuncSetAttribute(qkv_mma,
                         cudaFuncAttributeMaxDynamicSharedMemorySize, QSMEM);
    cudaFuncSetAttribute(mma_gemm<CC / 32, true, false>,
                         cudaFuncAttributeMaxDynamicSharedMemorySize, G_SMEM);
    cudaFuncSetAttribute(mma_gemm<NN / 32, false, true>,
                         cudaFuncAttributeMaxDynamicSharedMemorySize, G_SMEM);

    dim3 blk(256);
    xsplit_kernel<<<dim3(NN / 32, CC / 32, BB), blk>>>(x);
    wsplit_kernel<<<dim3(CC, 3), blk>>>(Wq, Wk, Wv);
    qkv_mma<<<dim3(NN / 128, CC / 64, BB), blk, QSMEM>>>(bq, bk, bv);

    // scores: C[n][m] = 1/16 * Q[n][:] . K[m][:]   (K=256), single-pass bf16
    mma_gemm<CC / 32, true, false><<<dim3(NN / 128, NN / 128, BB), blk, G_SMEM>>>(
        (const __nv_bfloat16*)pQh, (const __nv_bfloat16*)pKh,
        (float*)pS, nullptr,
        CC, CC, NN, 1.0f / 16.0f,
        (size_t)NN * CC, (size_t)NN * CC, (size_t)NN * NN);

    softmax_kernel<<<BB * NN, 256>>>();

    // out: C[c][n] = V[c][:] . P[n][:]  (K=2048) + x, single-pass bf16
    mma_gemm<NN / 32, false, true><<<dim3(NN / 128, CC / 128, BB), blk, G_SMEM>>>(
        (const __nv_bfloat16*)pVh, (const __nv_bfloat16*)pPh,
        out, x,
        NN, NN, NN, 1.0f,
        (size_t)CC * NN, (size_t)NN * NN, (size_t)CC * NN);
}

// round 9
// speedup vs baseline: 2.2351x; 1.1733x over previous
#include <cuda_runtime.h>
#include <cuda_bf16.h>
#include <cstdint>

#define BB 8
#define CC 256
#define NN 2048

// ---------------- scratch (device globals; no allocs) ----------------------
__device__ __nv_bfloat16 g_Xh[BB * NN * CC];                       // xT [b][n][c]
__device__ __nv_bfloat16 g_Wh[3 * CC * CC];                        // Wq,Wk,Wv bf16
__device__ __nv_bfloat16 g_Qh[BB * NN * CC];                       // [b][n][c]
__device__ __nv_bfloat16 g_Kh[BB * NN * CC];                       // [b][m][c]
__device__ __nv_bfloat16 g_Vh[BB * CC * NN];                       // [b][c][m]
__device__ float         g_S [(size_t)BB * NN * NN];               // fp32 scores
__device__ __nv_bfloat16 g_Ph[(size_t)BB * NN * NN];               // probs (bf16)

// ---------------- PTX helpers (baseline PTX only) ---------------------------
__device__ __forceinline__ uint32_t smem_u32(const void* p) {
    uint32_t a;
    asm("{ .reg .u64 t; cvta.to.shared.u64 t, %1; cvt.u32.u64 %0, t; }"
        : "=r"(a) : "l"(p));
    return a;
}

#define CP_ASYNC16(dst, src) \
    asm volatile("cp.async.cg.shared.global [%0], [%1], 16;" \
                 :: "r"(dst), "l"(src) : "memory")
#define CP_COMMIT() asm volatile("cp.async.commit_group;" ::: "memory")
#define CP_WAIT(n)  asm volatile("cp.async.wait_group %0;" :: "n"(n) : "memory")

#define LDSM_X4(r0, r1, r2, r3, addr) \
    asm volatile("ldmatrix.sync.aligned.m8n8.x4.shared.b16 {%0,%1,%2,%3}, [%4];" \
                 : "=r"(r0), "=r"(r1), "=r"(r2), "=r"(r3) : "r"(addr))

#define MMA16816(c, a, b0, b1) \
    asm volatile("mma.sync.aligned.m16n8k16.row.col.f32.bf16.bf16.f32 " \
                 "{%0,%1,%2,%3}, {%4,%5,%6,%7}, {%8,%9}, {%0,%1,%2,%3};" \
                 : "+f"((c)[0]), "+f"((c)[1]), "+f"((c)[2]), "+f"((c)[3]) \
                 : "r"((a)[0]), "r"((a)[1]), "r"((a)[2]), "r"((a)[3]), \
                   "r"(b0), "r"(b1))

__device__ __forceinline__ __nv_bfloat16 bsplit_hi(float v) { return __float2bfloat16(v); }

#define ROW_STRIDE 80
#define TILE_BYTES 10240            // 128 rows * 80 B (one 32-col chunk-tile)
// single-pass gemm: BK=64 -> stage = [A0|B0|A1|B1], 2-stage ring
#define S_STAGE    (4 * TILE_BYTES)         // 40960
#define G_SMEM     (2 * S_STAGE)            // 81920
// qkv kernel smem: stage = A chunk (128 rows) + 3 W chunk tiles (64 rows)
#define QB_TILE    5120
#define QBUF       (TILE_BYTES + 3 * QB_TILE)   // 25600
#define QSMEM      (2 * QBUF)                   // 51200

// ---------------------------------------------------------------------------
// xsplit: x [b][c][n] fp32 -> xT [b][n][c] bf16
// ---------------------------------------------------------------------------
__global__ __launch_bounds__(256) void xsplit_kernel(const float* __restrict__ x)
{
    __shared__ float t[32][33];
    const int n0 = blockIdx.x * 32;
    const int c0 = blockIdx.y * 32;
    const int b  = blockIdx.z;
    const int tx = threadIdx.x & 31;
    const int ty = threadIdx.x >> 5;

    #pragma unroll
    for (int k = 0; k < 4; k++)
        t[ty + k * 8][tx] = x[((size_t)b * CC + c0 + ty + k * 8) * NN + n0 + tx];
    __syncthreads();
    #pragma unroll
    for (int k = 0; k < 4; k++) {
        const float v = t[tx][ty + k * 8];
        const size_t idx = ((size_t)b * NN + n0 + ty + k * 8) * CC + c0 + tx;
        g_Xh[idx] = bsplit_hi(v);
    }
}

// ---------------------------------------------------------------------------
// wsplit: Wq/Wk/Wv fp32 -> bf16
// ---------------------------------------------------------------------------
__global__ __launch_bounds__(256) void wsplit_kernel(
    const float* __restrict__ Wq, const float* __restrict__ Wk,
    const float* __restrict__ Wv)
{
    const int m = blockIdx.y;
    const int e = blockIdx.x * 256 + threadIdx.x;
    const float v = (m == 0 ? Wq : (m == 1 ? Wk : Wv))[e];
    g_Wh[m * CC * CC + e] = bsplit_hi(v);
}

// ---------------------------------------------------------------------------
// qkv_mma: single-pass bf16 HMMA projection, fused Q/K/V.
// CTA tile 128n x 64o, 8 warps (wm 0..3 n, wn 0..1 o).
// (issue ordering here was always after the trailing barrier — correct.)
// ---------------------------------------------------------------------------
__global__ __launch_bounds__(256) void qkv_mma(
    const float* __restrict__ bq, const float* __restrict__ bk,
    const float* __restrict__ bv)
{
    extern __shared__ __align__(16) char sm[];
    const int n0 = blockIdx.x * 128;
    const int o0 = blockIdx.y * 64;
    const int b  = blockIdx.z;

    const int tid  = threadIdx.x;
    const int wid  = tid >> 5;
    const int lane = tid & 31;
    const int wn   = wid & 1;
    const int wm   = wid >> 1;

    const uint32_t smbase = smem_u32(sm);

    const __nv_bfloat16* gX = g_Xh + ((size_t)b * NN + n0) * CC;
    const __nv_bfloat16* W3[3] = { g_Wh, g_Wh + CC * CC, g_Wh + 2 * CC * CC };

    const uint32_t offA = (uint32_t)((lane & 15) * ROW_STRIDE + (lane >> 4) * 16);
    const uint32_t offB = (uint32_t)(((lane & 7) + ((lane >> 4) << 3)) * ROW_STRIDE
                                     + (((lane >> 3) & 1) << 4));

    float acc[3][2][4][4] = {};

    const int alr = tid >> 1, alc = (tid & 1) * 2;
    const int brb = tid >> 2, bcb = tid & 3;

    auto issue = [&](int buf, int k0) {
        const uint32_t base = smbase + buf * QBUF;
        #pragma unroll
        for (int c = 0; c < 2; c++) {
            const int chunk = alc + c;
            CP_ASYNC16(base + (uint32_t)(alr * ROW_STRIDE + chunk * 16),
                       gX + (size_t)alr * CC + k0 + chunk * 8);
        }
        const uint32_t sob = base + TILE_BYTES
                           + (uint32_t)(brb * ROW_STRIDE + bcb * 16);
        const size_t gwb = (size_t)(o0 + brb) * CC + k0 + bcb * 8;
        #pragma unroll
        for (int m = 0; m < 3; m++)
            CP_ASYNC16(sob + m * QB_TILE, W3[m] + gwb);
        CP_COMMIT();
    };

    issue(0, 0);
    issue(1, 32);

    #pragma unroll 1
    for (int t = 0; t < 8; t++) {
        if (t == 7) { CP_WAIT(0); } else { CP_WAIT(1); }
        __syncthreads();
        const uint32_t base = smbase + (t & 1) * QBUF;

        #pragma unroll
        for (int ks = 0; ks < 2; ks++) {
            const uint32_t kb2 = ks * 32;
            uint32_t ah[2][4];
            #pragma unroll
            for (int mt = 0; mt < 2; mt++) {
                const uint32_t toff = (uint32_t)((wm * 32 + mt * 16) * ROW_STRIDE) + kb2 + offA;
                LDSM_X4(ah[mt][0], ah[mt][1], ah[mt][2], ah[mt][3], base + toff);
            }
            #pragma unroll
            for (int q = 0; q < 3; q++) {
                uint32_t bh[4][2];
                #pragma unroll
                for (int g = 0; g < 2; g++) {
                    const uint32_t toffb = (uint32_t)((wn * 32 + g * 16) * ROW_STRIDE) + kb2 + offB;
                    LDSM_X4(bh[2*g][0], bh[2*g][1], bh[2*g+1][0], bh[2*g+1][1],
                            base + TILE_BYTES + q * QB_TILE + toffb);
                }
                #pragma unroll
                for (int mt = 0; mt < 2; mt++)
                    #pragma unroll
                    for (int nt = 0; nt < 4; nt++)
                        MMA16816(acc[q][mt][nt], ah[mt], bh[nt][0], bh[nt][1]);
            }
        }
        __syncthreads();
        if (t + 2 < 8) issue(t & 1, (t + 2) * 32);
    }

    const int g  = lane >> 2;
    const int tq = lane & 3;

    // Q, K stores [n][c]
    #pragma unroll
    for (int mt = 0; mt < 2; mt++)
        #pragma unroll
        for (int h = 0; h < 2; h++) {
            const int n = n0 + wm * 32 + mt * 16 + g + h * 8;
            #pragma unroll
            for (int nt = 0; nt < 4; nt++) {
                const int col = o0 + wn * 32 + nt * 8 + tq * 2;
                const size_t idx = ((size_t)b * NN + n) * CC + col;
                const float q0 = acc[0][mt][nt][2*h]   + bq[col];
                const float q1 = acc[0][mt][nt][2*h+1] + bq[col + 1];
                const float k0v = acc[1][mt][nt][2*h]   + bk[col];
                const float k1v = acc[1][mt][nt][2*h+1] + bk[col + 1];
                *(__nv_bfloat162*)&g_Qh[idx] = __halves2bfloat162(bsplit_hi(q0), bsplit_hi(q1));
                *(__nv_bfloat162*)&g_Kh[idx] = __halves2bfloat162(bsplit_hi(k0v), bsplit_hi(k1v));
            }
        }

    // V: stage fp32 in smem, transpose to [c][n]
    __syncthreads();
    float* vbuf = (float*)sm;
    #pragma unroll
    for (int mt = 0; mt < 2; mt++)
        #pragma unroll
        for (int h = 0; h < 2; h++) {
            const int row = wm * 32 + mt * 16 + g + h * 8;
            #pragma unroll
            for (int nt = 0; nt < 4; nt++) {
                const int col = wn * 32 + nt * 8 + tq * 2;
                vbuf[row * 65 + col]     = acc[2][mt][nt][2*h]   + bv[o0 + col];
                vbuf[row * 65 + col + 1] = acc[2][mt][nt][2*h+1] + bv[o0 + col + 1];
            }
        }
    __syncthreads();
    #pragma unroll
    for (int cr = 0; cr < 8; cr++) {
        const int c = wid * 8 + cr;
        const size_t obase = ((size_t)b * CC + o0 + c) * NN + n0;
        #pragma unroll
        for (int it = 0; it < 2; it++) {
            const int nl = it * 64 + lane * 2;
            const float f0 = vbuf[nl * 65 + c];
            const float f1 = vbuf[(nl + 1) * 65 + c];
            *(__nv_bfloat162*)&g_Vh[obase + nl]
                = __halves2bfloat162(bsplit_hi(f0), bsplit_hi(f1));
        }
    }
}

// ---------------------------------------------------------------------------
// Single-pass bf16 NT GEMM, BK=64 per barrier, 2-stage cp.async ring.
//   C[i][j] = s * sum_k A[i][k]*B[j][k]  (+ R[i][j])
// 128x128 tile, 256 thr (8 warps 2x4), warp 64x32.
// FIX vs R8: prefetch of tile t+2 into buffer (t&1) is issued ONLY after the
// trailing __syncthreads() that proves every warp finished reading buffer t&1.
// ---------------------------------------------------------------------------
template<int KTILES64, bool SCALE, bool RESID>
__global__ __launch_bounds__(256, 2) void mma_gemm(
    const __nv_bfloat16* __restrict__ A, const __nv_bfloat16* __restrict__ B,
    float* __restrict__ C, const float* __restrict__ R,
    int lda, int ldb, int ldc, float scale,
    size_t sA, size_t sB, size_t sC)
{
    extern __shared__ __align__(16) char sm[];

    const int j0 = blockIdx.x * 128;
    const int i0 = blockIdx.y * 128;
    const int b  = blockIdx.z;

    const int tid  = threadIdx.x;
    const int lane = tid & 31;
    const int wid  = tid >> 5;
    const int wm   = wid >> 2;
    const int wn   = wid & 3;

    const __nv_bfloat16* gA = A + (size_t)b * sA;
    const __nv_bfloat16* gB = B + (size_t)b * sB;

    const int lr = tid >> 1;
    const int lc = (tid & 1) * 2;
    const uint32_t smbase = smem_u32(sm);

    const uint32_t offA = (uint32_t)((lane & 15) * ROW_STRIDE + (lane >> 4) * 16);
    const uint32_t offB = (uint32_t)(((lane & 7) + ((lane >> 4) << 3)) * ROW_STRIDE
                                     + (((lane >> 3) & 1) << 4));

    float acc[4][4][4] = {};

    auto issue = [&](int buf, int k0) {
        const uint32_t base = smbase + buf * S_STAGE;
        #pragma unroll
        for (int cnk = 0; cnk < 2; cnk++) {
            const uint32_t cb = base + cnk * (2 * TILE_BYTES);
            #pragma unroll
            for (int c = 0; c < 2; c++) {
                const int chunk = lc + c;
                const uint32_t so = cb + (uint32_t)(lr * ROW_STRIDE + chunk * 16);
                const int gk = k0 + cnk * 32 + chunk * 8;
                CP_ASYNC16(so,              gA + (size_t)(i0 + lr) * lda + gk);
                CP_ASYNC16(so + TILE_BYTES, gB + (size_t)(j0 + lr) * ldb + gk);
            }
        }
        CP_COMMIT();
    };

    issue(0, 0);
    issue(1, 64);

    #pragma unroll 1
    for (int t = 0; t < KTILES64; t++) {
        if (t == KTILES64 - 1) { CP_WAIT(0); } else { CP_WAIT(1); }
        __syncthreads();

        const uint32_t base = smbase + (t & 1) * S_STAGE;

        #pragma unroll
        for (int cnk = 0; cnk < 2; cnk++) {
            const uint32_t aA = base + cnk * (2 * TILE_BYTES);
            const uint32_t aB = aA + TILE_BYTES;
            #pragma unroll
            for (int ks = 0; ks < 2; ks++) {
                const uint32_t kb2 = ks * 32;
                uint32_t ahf[4][4];
                #pragma unroll
                for (int mt = 0; mt < 4; mt++) {
                    const uint32_t toff = (uint32_t)((wm * 64 + mt * 16) * ROW_STRIDE) + kb2 + offA;
                    LDSM_X4(ahf[mt][0], ahf[mt][1], ahf[mt][2], ahf[mt][3], aA + toff);
                }
                uint32_t bhf[4][2];
                #pragma unroll
                for (int g = 0; g < 2; g++) {
                    const uint32_t toff = (uint32_t)((wn * 32 + g * 16) * ROW_STRIDE) + kb2 + offB;
                    LDSM_X4(bhf[2*g][0], bhf[2*g][1], bhf[2*g+1][0], bhf[2*g+1][1], aB + toff);
                }
                #pragma unroll
                for (int mt = 0; mt < 4; mt++)
                    #pragma unroll
                    for (int nt = 0; nt < 4; nt++)
                        MMA16816(acc[mt][nt], ahf[mt], bhf[nt][0], bhf[nt][1]);
            }
        }

        __syncthreads();                 // all warps done reading buffer t&1
        if (t + 2 < KTILES64) issue(t & 1, (t + 2) * 64);
    }

    const int g  = lane >> 2;
    const int tq = lane & 3;
    float* Cb = C + (size_t)b * sC;
    const float* Rb = R + (size_t)b * sC;

    #pragma unroll
    for (int mt = 0; mt < 4; mt++) {
        const int row0 = i0 + wm * 64 + mt * 16 + g;
        #pragma unroll
        for (int nt = 0; nt < 4; nt++) {
            const int col = j0 + wn * 32 + nt * 8 + tq * 2;
            float2 v0 = make_float2(acc[mt][nt][0], acc[mt][nt][1]);
            float2 v1 = make_float2(acc[mt][nt][2], acc[mt][nt][3]);
            if (SCALE) { v0.x *= scale; v0.y *= scale; v1.x *= scale; v1.y *= scale; }
            const size_t idx0 = (size_t)row0 * ldc + col;
            const size_t idx1 = (size_t)(row0 + 8) * ldc + col;
            if (RESID) {
                float2 r0 = *(const float2*)&Rb[idx0];
                float2 r1 = *(const float2*)&Rb[idx1];
                v0.x += r0.x; v0.y += r0.y; v1.x += r1.x; v1.y += r1.y;
            }
            *(float2*)&Cb[idx0] = v0;
            *(float2*)&Cb[idx1] = v1;
        }
    }
}

// ---------------------------------------------------------------------------
// softmax: fp32 scores -> bf16 probs.
// ---------------------------------------------------------------------------
__global__ __launch_bounds__(256) void softmax_kernel()
{
    __shared__ float redmax[8];
    __shared__ float redsum[8];

    const size_t row = blockIdx.x;
    const float* p = g_S + row * NN;
    __nv_bfloat16* ph = g_Ph + row * NN;
    const int tid  = threadIdx.x;
    const int lane = tid & 31;
    const int warp = tid >> 5;

    float v[8];
    float mx = -3.4e38f;
    #pragma unroll
    for (int t = 0; t < 8; t++) {
        v[t] = p[tid + t * 256];
        mx = fmaxf(mx, v[t]);
    }
    #pragma unroll
    for (int o = 16; o > 0; o >>= 1)
        mx = fmaxf(mx, __shfl_xor_sync(0xffffffffu, mx, o));
    if (lane == 0) redmax[warp] = mx;
    __syncthreads();
    if (warp == 0) {
        float w = (lane < 8) ? redmax[lane] : -3.4e38f;
        #pragma unroll
        for (int o = 4; o > 0; o >>= 1)
            w = fmaxf(w, __shfl_xor_sync(0xffffffffu, w, o));
        if (lane == 0) redmax[0] = w;
    }
    __syncthreads();
    mx = redmax[0];

    float s = 0.0f;
    #pragma unroll
    for (int t = 0; t < 8; t++) {
        v[t] = __expf(v[t] - mx);
        s += v[t];
    }
    #pragma unroll
    for (int o = 16; o > 0; o >>= 1)
        s += __shfl_xor_sync(0xffffffffu, s, o);
    if (lane == 0) redsum[warp] = s;
    __syncthreads();
    if (warp == 0) {
        float w = (lane < 8) ? redsum[lane] : 0.0f;
        #pragma unroll
        for (int o = 4; o > 0; o >>= 1)
            w += __shfl_xor_sync(0xffffffffu, w, o);
        if (lane == 0) redsum[0] = w;
    }
    __syncthreads();
    const float inv = 1.0f / redsum[0];

    #pragma unroll
    for (int t = 0; t < 8; t++)
        ph[tid + t * 256] = bsplit_hi(v[t] * inv);
}

// ---------------------------------------------------------------------------
extern "C" void kernel_launch(void* const* d_in, const int* in_sizes, int n_in,
                              void* d_out, int out_size)
{
    const float* x  = (const float*)d_in[0];
    const float* Wq = (const float*)d_in[1];
    const float* bq = (const float*)d_in[2];
    const float* Wk = (const float*)d_in[3];
    const float* bk = (const float*)d_in[4];
    const float* Wv = (const float*)d_in[5];
    const float* bv = (const float*)d_in[6];
    float* out = (float*)d_out;

    void *pQh, *pKh, *pVh, *pS, *pPh;
    cudaGetSymbolAddress(&pQh, g_Qh);
    cudaGetSymbolAddress(&pKh, g_Kh);
    cudaGetSymbolAddress(&pVh, g_Vh);
    cudaGetSymbolAddress(&pS,  g_S);
    cudaGetSymbolAddress(&pPh, g_Ph);

    cudaFuncSetAttribute(qkv_mma,
                         cudaFuncAttributeMaxDynamicSharedMemorySize, QSMEM);
    cudaFuncSetAttribute(mma_gemm<CC / 64, true, false>,
                         cudaFuncAttributeMaxDynamicSharedMemorySize, G_SMEM);
    cudaFuncSetAttribute(mma_gemm<NN / 64, false, true>,
                         cudaFuncAttributeMaxDynamicSharedMemorySize, G_SMEM);

    dim3 blk(256);
    xsplit_kernel<<<dim3(NN / 32, CC / 32, BB), blk>>>(x);
    wsplit_kernel<<<dim3(CC, 3), blk>>>(Wq, Wk, Wv);
    qkv_mma<<<dim3(NN / 128, CC / 64, BB), blk, QSMEM>>>(bq, bk, bv);

    // scores: C[n][m] = 1/16 * Q[n][:] . K[m][:]   (K=256)
    mma_gemm<CC / 64, true, false><<<dim3(NN / 128, NN / 128, BB), blk, G_SMEM>>>(
        (const __nv_bfloat16*)pQh, (const __nv_bfloat16*)pKh,
        (float*)pS, nullptr,
        CC, CC, NN, 1.0f / 16.0f,
        (size_t)NN * CC, (size_t)NN * CC, (size_t)NN * NN);

    softmax_kernel<<<BB * NN, 256>>>();

    // out: C[c][n] = V[c][:] . P[n][:]  (K=2048) + x
    mma_gemm<NN / 64, false, true><<<dim3(NN / 128, CC / 128, BB), blk, G_SMEM>>>(
        (const __nv_bfloat16*)pVh, (const __nv_bfloat16*)pPh,
        out, x,
        NN, NN, NN, 1.0f,
        (size_t)CC * NN, (size_t)NN * NN, (size_t)CC * NN);
}

// round 10
// speedup vs baseline: 2.3163x; 1.0363x over previous
#include <cuda_runtime.h>
#include <cuda_bf16.h>
#include <cuda_fp16.h>
#include <cstdint>

#define BB 8
#define CC 256
#define NN 2048

// ---------------- scratch (device globals; no allocs) ----------------------
__device__ __nv_bfloat16 g_Xh[BB * NN * CC];                       // xT [b][n][c]
__device__ __nv_bfloat16 g_Wh[3 * CC * CC];                        // Wq,Wk,Wv bf16
__device__ __nv_bfloat16 g_Qh[BB * NN * CC];                       // [b][n][c]
__device__ __nv_bfloat16 g_Kh[BB * NN * CC];                       // [b][m][c]
__device__ __nv_bfloat16 g_Vh[BB * CC * NN];                       // [b][c][m]
__device__ __half        g_S [(size_t)BB * NN * NN];               // fp16 scores
__device__ __nv_bfloat16 g_Ph[(size_t)BB * NN * NN];               // probs (bf16)

// ---------------- PTX helpers (baseline PTX only) ---------------------------
__device__ __forceinline__ uint32_t smem_u32(const void* p) {
    uint32_t a;
    asm("{ .reg .u64 t; cvta.to.shared.u64 t, %1; cvt.u32.u64 %0, t; }"
        : "=r"(a) : "l"(p));
    return a;
}

#define CP_ASYNC16(dst, src) \
    asm volatile("cp.async.cg.shared.global [%0], [%1], 16;" \
                 :: "r"(dst), "l"(src) : "memory")
#define CP_COMMIT() asm volatile("cp.async.commit_group;" ::: "memory")
#define CP_WAIT(n)  asm volatile("cp.async.wait_group %0;" :: "n"(n) : "memory")

#define LDSM_X4(r0, r1, r2, r3, addr) \
    asm volatile("ldmatrix.sync.aligned.m8n8.x4.shared.b16 {%0,%1,%2,%3}, [%4];" \
                 : "=r"(r0), "=r"(r1), "=r"(r2), "=r"(r3) : "r"(addr))

#define MMA16816(c, a, b0, b1) \
    asm volatile("mma.sync.aligned.m16n8k16.row.col.f32.bf16.bf16.f32 " \
                 "{%0,%1,%2,%3}, {%4,%5,%6,%7}, {%8,%9}, {%0,%1,%2,%3};" \
                 : "+f"((c)[0]), "+f"((c)[1]), "+f"((c)[2]), "+f"((c)[3]) \
                 : "r"((a)[0]), "r"((a)[1]), "r"((a)[2]), "r"((a)[3]), \
                   "r"(b0), "r"(b1))

__device__ __forceinline__ __nv_bfloat16 bsplit_hi(float v) { return __float2bfloat16(v); }

#define ROW_STRIDE 80
#define TILE_BYTES 10240            // 128 rows * 80 B (one 32-col chunk-tile)
// single-pass gemm: BK=64 -> stage = [A0|B0|A1|B1], 2-stage ring
#define S_STAGE    (4 * TILE_BYTES)         // 40960
#define G_SMEM     (2 * S_STAGE)            // 81920
// qkv kernel smem: stage = A chunk (128 rows) + 3 W chunk tiles (64 rows)
#define QB_TILE    5120
#define QBUF       (TILE_BYTES + 3 * QB_TILE)   // 25600
#define QSMEM      (2 * QBUF)                   // 51200

// ---------------------------------------------------------------------------
// xsplit: x [b][c][n] fp32 -> xT [b][n][c] bf16
// ---------------------------------------------------------------------------
__global__ __launch_bounds__(256) void xsplit_kernel(const float* __restrict__ x)
{
    __shared__ float t[32][33];
    const int n0 = blockIdx.x * 32;
    const int c0 = blockIdx.y * 32;
    const int b  = blockIdx.z;
    const int tx = threadIdx.x & 31;
    const int ty = threadIdx.x >> 5;

    #pragma unroll
    for (int k = 0; k < 4; k++)
        t[ty + k * 8][tx] = x[((size_t)b * CC + c0 + ty + k * 8) * NN + n0 + tx];
    __syncthreads();
    #pragma unroll
    for (int k = 0; k < 4; k++) {
        const float v = t[tx][ty + k * 8];
        const size_t idx = ((size_t)b * NN + n0 + ty + k * 8) * CC + c0 + tx;
        g_Xh[idx] = bsplit_hi(v);
    }
}

// ---------------------------------------------------------------------------
// wsplit: Wq/Wk/Wv fp32 -> bf16
// ---------------------------------------------------------------------------
__global__ __launch_bounds__(256) void wsplit_kernel(
    const float* __restrict__ Wq, const float* __restrict__ Wk,
    const float* __restrict__ Wv)
{
    const int m = blockIdx.y;
    const int e = blockIdx.x * 256 + threadIdx.x;
    const float v = (m == 0 ? Wq : (m == 1 ? Wk : Wv))[e];
    g_Wh[m * CC * CC + e] = bsplit_hi(v);
}

// ---------------------------------------------------------------------------
// qkv_mma: single-pass bf16 HMMA projection, fused Q/K/V (proven R9 version).
// ---------------------------------------------------------------------------
__global__ __launch_bounds__(256) void qkv_mma(
    const float* __restrict__ bq, const float* __restrict__ bk,
    const float* __restrict__ bv)
{
    extern __shared__ __align__(16) char sm[];
    const int n0 = blockIdx.x * 128;
    const int o0 = blockIdx.y * 64;
    const int b  = blockIdx.z;

    const int tid  = threadIdx.x;
    const int wid  = tid >> 5;
    const int lane = tid & 31;
    const int wn   = wid & 1;
    const int wm   = wid >> 1;

    const uint32_t smbase = smem_u32(sm);

    const __nv_bfloat16* gX = g_Xh + ((size_t)b * NN + n0) * CC;
    const __nv_bfloat16* W3[3] = { g_Wh, g_Wh + CC * CC, g_Wh + 2 * CC * CC };

    const uint32_t offA = (uint32_t)((lane & 15) * ROW_STRIDE + (lane >> 4) * 16);
    const uint32_t offB = (uint32_t)(((lane & 7) + ((lane >> 4) << 3)) * ROW_STRIDE
                                     + (((lane >> 3) & 1) << 4));

    float acc[3][2][4][4] = {};

    const int alr = tid >> 1, alc = (tid & 1) * 2;
    const int brb = tid >> 2, bcb = tid & 3;

    auto issue = [&](int buf, int k0) {
        const uint32_t base = smbase + buf * QBUF;
        #pragma unroll
        for (int c = 0; c < 2; c++) {
            const int chunk = alc + c;
            CP_ASYNC16(base + (uint32_t)(alr * ROW_STRIDE + chunk * 16),
                       gX + (size_t)alr * CC + k0 + chunk * 8);
        }
        const uint32_t sob = base + TILE_BYTES
                           + (uint32_t)(brb * ROW_STRIDE + bcb * 16);
        const size_t gwb = (size_t)(o0 + brb) * CC + k0 + bcb * 8;
        #pragma unroll
        for (int m = 0; m < 3; m++)
            CP_ASYNC16(sob + m * QB_TILE, W3[m] + gwb);
        CP_COMMIT();
    };

    issue(0, 0);
    issue(1, 32);

    #pragma unroll 1
    for (int t = 0; t < 8; t++) {
        if (t == 7) { CP_WAIT(0); } else { CP_WAIT(1); }
        __syncthreads();
        const uint32_t base = smbase + (t & 1) * QBUF;

        #pragma unroll
        for (int ks = 0; ks < 2; ks++) {
            const uint32_t kb2 = ks * 32;
            uint32_t ah[2][4];
            #pragma unroll
            for (int mt = 0; mt < 2; mt++) {
                const uint32_t toff = (uint32_t)((wm * 32 + mt * 16) * ROW_STRIDE) + kb2 + offA;
                LDSM_X4(ah[mt][0], ah[mt][1], ah[mt][2], ah[mt][3], base + toff);
            }
            #pragma unroll
            for (int q = 0; q < 3; q++) {
                uint32_t bh[4][2];
                #pragma unroll
                for (int g = 0; g < 2; g++) {
                    const uint32_t toffb = (uint32_t)((wn * 32 + g * 16) * ROW_STRIDE) + kb2 + offB;
                    LDSM_X4(bh[2*g][0], bh[2*g][1], bh[2*g+1][0], bh[2*g+1][1],
                            base + TILE_BYTES + q * QB_TILE + toffb);
                }
                #pragma unroll
                for (int mt = 0; mt < 2; mt++)
                    #pragma unroll
                    for (int nt = 0; nt < 4; nt++)
                        MMA16816(acc[q][mt][nt], ah[mt], bh[nt][0], bh[nt][1]);
            }
        }
        __syncthreads();
        if (t + 2 < 8) issue(t & 1, (t + 2) * 32);
    }

    const int g  = lane >> 2;
    const int tq = lane & 3;

    // Q, K stores [n][c]
    #pragma unroll
    for (int mt = 0; mt < 2; mt++)
        #pragma unroll
        for (int h = 0; h < 2; h++) {
            const int n = n0 + wm * 32 + mt * 16 + g + h * 8;
            #pragma unroll
            for (int nt = 0; nt < 4; nt++) {
                const int col = o0 + wn * 32 + nt * 8 + tq * 2;
                const size_t idx = ((size_t)b * NN + n) * CC + col;
                const float q0 = acc[0][mt][nt][2*h]   + bq[col];
                const float q1 = acc[0][mt][nt][2*h+1] + bq[col + 1];
                const float k0v = acc[1][mt][nt][2*h]   + bk[col];
                const float k1v = acc[1][mt][nt][2*h+1] + bk[col + 1];
                *(__nv_bfloat162*)&g_Qh[idx] = __halves2bfloat162(bsplit_hi(q0), bsplit_hi(q1));
                *(__nv_bfloat162*)&g_Kh[idx] = __halves2bfloat162(bsplit_hi(k0v), bsplit_hi(k1v));
            }
        }

    // V: stage fp32 in smem, transpose to [c][n]
    __syncthreads();
    float* vbuf = (float*)sm;
    #pragma unroll
    for (int mt = 0; mt < 2; mt++)
        #pragma unroll
        for (int h = 0; h < 2; h++) {
            const int row = wm * 32 + mt * 16 + g + h * 8;
            #pragma unroll
            for (int nt = 0; nt < 4; nt++) {
                const int col = wn * 32 + nt * 8 + tq * 2;
                vbuf[row * 65 + col]     = acc[2][mt][nt][2*h]   + bv[o0 + col];
                vbuf[row * 65 + col + 1] = acc[2][mt][nt][2*h+1] + bv[o0 + col + 1];
            }
        }
    __syncthreads();
    #pragma unroll
    for (int cr = 0; cr < 8; cr++) {
        const int c = wid * 8 + cr;
        const size_t obase = ((size_t)b * CC + o0 + c) * NN + n0;
        #pragma unroll
        for (int it = 0; it < 2; it++) {
            const int nl = it * 64 + lane * 2;
            const float f0 = vbuf[nl * 65 + c];
            const float f1 = vbuf[(nl + 1) * 65 + c];
            *(__nv_bfloat162*)&g_Vh[obase + nl]
                = __halves2bfloat162(bsplit_hi(f0), bsplit_hi(f1));
        }
    }
}

// ---------------------------------------------------------------------------
// Single-pass bf16 NT GEMM, BK=64 per barrier, 2-stage cp.async ring.
//   C[i][j] = s * sum_k A[i][k]*B[j][k]  (+ R[i][j])
// TOUT = __half (scores, scaled) or float (out, +residual).
// ---------------------------------------------------------------------------
template<int KTILES64, bool SCALE, bool RESID, typename TOUT>
__global__ __launch_bounds__(256, 2) void mma_gemm(
    const __nv_bfloat16* __restrict__ A, const __nv_bfloat16* __restrict__ B,
    TOUT* __restrict__ C, const float* __restrict__ R,
    int lda, int ldb, int ldc, float scale,
    size_t sA, size_t sB, size_t sC)
{
    extern __shared__ __align__(16) char sm[];

    const int j0 = blockIdx.x * 128;
    const int i0 = blockIdx.y * 128;
    const int b  = blockIdx.z;

    const int tid  = threadIdx.x;
    const int lane = tid & 31;
    const int wid  = tid >> 5;
    const int wm   = wid >> 2;
    const int wn   = wid & 3;

    const __nv_bfloat16* gA = A + (size_t)b * sA;
    const __nv_bfloat16* gB = B + (size_t)b * sB;

    const int lr = tid >> 1;
    const int lc = (tid & 1) * 2;
    const uint32_t smbase = smem_u32(sm);

    const uint32_t offA = (uint32_t)((lane & 15) * ROW_STRIDE + (lane >> 4) * 16);
    const uint32_t offB = (uint32_t)(((lane & 7) + ((lane >> 4) << 3)) * ROW_STRIDE
                                     + (((lane >> 3) & 1) << 4));

    float acc[4][4][4] = {};

    auto issue = [&](int buf, int k0) {
        const uint32_t base = smbase + buf * S_STAGE;
        #pragma unroll
        for (int cnk = 0; cnk < 2; cnk++) {
            const uint32_t cb = base + cnk * (2 * TILE_BYTES);
            #pragma unroll
            for (int c = 0; c < 2; c++) {
                const int chunk = lc + c;
                const uint32_t so = cb + (uint32_t)(lr * ROW_STRIDE + chunk * 16);
                const int gk = k0 + cnk * 32 + chunk * 8;
                CP_ASYNC16(so,              gA + (size_t)(i0 + lr) * lda + gk);
                CP_ASYNC16(so + TILE_BYTES, gB + (size_t)(j0 + lr) * ldb + gk);
            }
        }
        CP_COMMIT();
    };

    issue(0, 0);
    issue(1, 64);

    #pragma unroll 1
    for (int t = 0; t < KTILES64; t++) {
        if (t == KTILES64 - 1) { CP_WAIT(0); } else { CP_WAIT(1); }
        __syncthreads();

        const uint32_t base = smbase + (t & 1) * S_STAGE;

        #pragma unroll
        for (int cnk = 0; cnk < 2; cnk++) {
            const uint32_t aA = base + cnk * (2 * TILE_BYTES);
            const uint32_t aB = aA + TILE_BYTES;
            #pragma unroll
            for (int ks = 0; ks < 2; ks++) {
                const uint32_t kb2 = ks * 32;
                uint32_t ahf[4][4];
                #pragma unroll
                for (int mt = 0; mt < 4; mt++) {
                    const uint32_t toff = (uint32_t)((wm * 64 + mt * 16) * ROW_STRIDE) + kb2 + offA;
                    LDSM_X4(ahf[mt][0], ahf[mt][1], ahf[mt][2], ahf[mt][3], aA + toff);
                }
                uint32_t bhf[4][2];
                #pragma unroll
                for (int g = 0; g < 2; g++) {
                    const uint32_t toff = (uint32_t)((wn * 32 + g * 16) * ROW_STRIDE) + kb2 + offB;
                    LDSM_X4(bhf[2*g][0], bhf[2*g][1], bhf[2*g+1][0], bhf[2*g+1][1], aB + toff);
                }
                #pragma unroll
                for (int mt = 0; mt < 4; mt++)
                    #pragma unroll
                    for (int nt = 0; nt < 4; nt++)
                        MMA16816(acc[mt][nt], ahf[mt], bhf[nt][0], bhf[nt][1]);
            }
        }

        __syncthreads();                 // all warps done reading buffer t&1
        if (t + 2 < KTILES64) issue(t & 1, (t + 2) * 64);
    }

    const int g  = lane >> 2;
    const int tq = lane & 3;
    TOUT* Cb = C + (size_t)b * sC;
    const float* Rb = R + (size_t)b * sC;

    #pragma unroll
    for (int mt = 0; mt < 4; mt++) {
        const int row0 = i0 + wm * 64 + mt * 16 + g;
        #pragma unroll
        for (int nt = 0; nt < 4; nt++) {
            const int col = j0 + wn * 32 + nt * 8 + tq * 2;
            float2 v0 = make_float2(acc[mt][nt][0], acc[mt][nt][1]);
            float2 v1 = make_float2(acc[mt][nt][2], acc[mt][nt][3]);
            if (SCALE) { v0.x *= scale; v0.y *= scale; v1.x *= scale; v1.y *= scale; }
            const size_t idx0 = (size_t)row0 * ldc + col;
            const size_t idx1 = (size_t)(row0 + 8) * ldc + col;
            if constexpr (RESID) {
                float2 r0 = *(const float2*)&Rb[idx0];
                float2 r1 = *(const float2*)&Rb[idx1];
                v0.x += r0.x; v0.y += r0.y; v1.x += r1.x; v1.y += r1.y;
            }
            if constexpr (sizeof(TOUT) == 2) {   // __half scores
                *(__half2*)&Cb[idx0] = __floats2half2_rn(v0.x, v0.y);
                *(__half2*)&Cb[idx1] = __floats2half2_rn(v1.x, v1.y);
            } else {                              // float out
                *(float2*)&Cb[idx0] = v0;
                *(float2*)&Cb[idx1] = v1;
            }
        }
    }
}

// ---------------------------------------------------------------------------
// softmax: fp16 scores -> bf16 probs. One uint4 load/store per thread.
// Thread t handles elems [t*8, t*8+8).
// ---------------------------------------------------------------------------
__global__ __launch_bounds__(256) void softmax_kernel()
{
    __shared__ float redmax[8];
    __shared__ float redsum[8];

    const size_t row = blockIdx.x;
    const __half* p = g_S + row * NN;
    __nv_bfloat16* ph = g_Ph + row * NN;
    const int tid  = threadIdx.x;
    const int lane = tid & 31;
    const int warp = tid >> 5;

    // load 8 consecutive halfs (16 B)
    uint4 raw = *(const uint4*)&p[tid * 8];
    const __half2* hp = (const __half2*)&raw;
    float v[8];
    #pragma unroll
    for (int q = 0; q < 4; q++) {
        float2 f = __half22float2(hp[q]);
        v[2*q] = f.x; v[2*q+1] = f.y;
    }

    float mx = -3.4e38f;
    #pragma unroll
    for (int t = 0; t < 8; t++) mx = fmaxf(mx, v[t]);
    #pragma unroll
    for (int o = 16; o > 0; o >>= 1)
        mx = fmaxf(mx, __shfl_xor_sync(0xffffffffu, mx, o));
    if (lane == 0) redmax[warp] = mx;
    __syncthreads();
    if (warp == 0) {
        float w = (lane < 8) ? redmax[lane] : -3.4e38f;
        #pragma unroll
        for (int o = 4; o > 0; o >>= 1)
            w = fmaxf(w, __shfl_xor_sync(0xffffffffu, w, o));
        if (lane == 0) redmax[0] = w;
    }
    __syncthreads();
    mx = redmax[0];

    float s = 0.0f;
    #pragma unroll
    for (int t = 0; t < 8; t++) {
        v[t] = __expf(v[t] - mx);
        s += v[t];
    }
    #pragma unroll
    for (int o = 16; o > 0; o >>= 1)
        s += __shfl_xor_sync(0xffffffffu, s, o);
    if (lane == 0) redsum[warp] = s;
    __syncthreads();
    if (warp == 0) {
        float w = (lane < 8) ? redsum[lane] : 0.0f;
        #pragma unroll
        for (int o = 4; o > 0; o >>= 1)
            w += __shfl_xor_sync(0xffffffffu, w, o);
        if (lane == 0) redsum[0] = w;
    }
    __syncthreads();
    const float inv = 1.0f / redsum[0];

    uint4 outw;
    __nv_bfloat162* op = (__nv_bfloat162*)&outw;
    #pragma unroll
    for (int q = 0; q < 4; q++)
        op[q] = __halves2bfloat162(bsplit_hi(v[2*q] * inv), bsplit_hi(v[2*q+1] * inv));
    *(uint4*)&ph[tid * 8] = outw;
}

// ---------------------------------------------------------------------------
extern "C" void kernel_launch(void* const* d_in, const int* in_sizes, int n_in,
                              void* d_out, int out_size)
{
    const float* x  = (const float*)d_in[0];
    const float* Wq = (const float*)d_in[1];
    const float* bq = (const float*)d_in[2];
    const float* Wk = (const float*)d_in[3];
    const float* bk = (const float*)d_in[4];
    const float* Wv = (const float*)d_in[5];
    const float* bv = (const float*)d_in[6];
    float* out = (float*)d_out;

    void *pQh, *pKh, *pVh, *pS, *pPh;
    cudaGetSymbolAddress(&pQh, g_Qh);
    cudaGetSymbolAddress(&pKh, g_Kh);
    cudaGetSymbolAddress(&pVh, g_Vh);
    cudaGetSymbolAddress(&pS,  g_S);
    cudaGetSymbolAddress(&pPh, g_Ph);

    cudaFuncSetAttribute(qkv_mma,
                         cudaFuncAttributeMaxDynamicSharedMemorySize, QSMEM);
    cudaFuncSetAttribute((const void*)mma_gemm<CC / 64, true, false, __half>,
                         cudaFuncAttributeMaxDynamicSharedMemorySize, G_SMEM);
    cudaFuncSetAttribute((const void*)mma_gemm<NN / 64, false, true, float>,
                         cudaFuncAttributeMaxDynamicSharedMemorySize, G_SMEM);

    dim3 blk(256);
    xsplit_kernel<<<dim3(NN / 32, CC / 32, BB), blk>>>(x);
    wsplit_kernel<<<dim3(CC, 3), blk>>>(Wq, Wk, Wv);
    qkv_mma<<<dim3(NN / 128, CC / 64, BB), blk, QSMEM>>>(bq, bk, bv);

    // scores: S[n][m] = 1/16 * Q[n][:] . K[m][:]   (K=256) -> fp16
    mma_gemm<CC / 64, true, false, __half><<<dim3(NN / 128, NN / 128, BB), blk, G_SMEM>>>(
        (const __nv_bfloat16*)pQh, (const __nv_bfloat16*)pKh,
        (__half*)pS, nullptr,
        CC, CC, NN, 1.0f / 16.0f,
        (size_t)NN * CC, (size_t)NN * CC, (size_t)NN * NN);

    softmax_kernel<<<BB * NN, 256>>>();

    // out: C[c][n] = V[c][:] . P[n][:]  (K=2048) + x
    mma_gemm<NN / 64, false, true, float><<<dim3(NN / 128, CC / 128, BB), blk, G_SMEM>>>(
        (const __nv_bfloat16*)pVh, (const __nv_bfloat16*)pPh,
        out, x,
        NN, NN, NN, 1.0f,
        (size_t)CC * NN, (size_t)NN * NN, (size_t)CC * NN);
}